// round 2
// baseline (speedup 1.0000x reference)
#include <cuda_runtime.h>
#include <cuda_bf16.h>

// Problem constants (from reference): B=32, T=512, D=768
#define LR_B 32
#define LR_T 512
#define LR_D 768

// Scratch (no cudaMalloc allowed): per-batch inclusive cumsum + totals
__device__ int g_cum[LR_B * LR_T];
__device__ int g_tot[LR_B];

// ---------------------------------------------------------------------------
// Kernel 1: per-batch rounded-duration inclusive scan.
// One block per batch, 512 threads, Hillis-Steele in shared memory.
// ---------------------------------------------------------------------------
__global__ void lr_scan_kernel(const float* __restrict__ dur) {
    const int b = blockIdx.x;
    const int i = threadIdx.x;
    __shared__ int s[LR_T];

    float d = dur[b * LR_T + i];
    // reps = floor(max(dur,0) + 0.5)  (identical fp32 ops to the reference)
    int r = (int)floorf(fmaxf(d, 0.0f) + 0.5f);
    s[i] = r;
    __syncthreads();

    #pragma unroll
    for (int off = 1; off < LR_T; off <<= 1) {
        int v = (i >= off) ? s[i - off] : 0;
        __syncthreads();
        s[i] += v;
        __syncthreads();
    }

    g_cum[b * LR_T + i] = s[i];
    if (i == LR_T - 1) g_tot[b] = s[i];
}

// ---------------------------------------------------------------------------
// Kernel 2: gather/expand. One block per output row (t, b).
// 192 threads * float4 = 768 floats = one D row, fully coalesced.
// idx = searchsorted(cum, t, side='right'), clamped to T-1.
// 10 binary-search steps (513 possible answers -> need 10, not 9!).
// Output stored with .cs (streaming) so the 210MB out-stream doesn't evict
// the 50MB x working set from L2.
// ---------------------------------------------------------------------------
__global__ void __launch_bounds__(192) lr_gather_kernel(
    const float* __restrict__ x,
    float* __restrict__ out,
    int t_out)
{
    const int t   = blockIdx.x;
    const int b   = blockIdx.y;
    const int tid = threadIdx.x;

    float4* orow = (float4*)(out + ((size_t)b * t_out + t) * LR_D);

    if (t >= g_tot[b]) {
        float4 z = make_float4(0.f, 0.f, 0.f, 0.f);
        asm volatile("st.global.cs.v4.f32 [%0], {%1,%2,%3,%4};"
                     :: "l"(orow + tid), "f"(z.x), "f"(z.y), "f"(z.z), "f"(z.w)
                     : "memory");
        return;
    }

    const int* cum = g_cum + b * LR_T;

    // Binary search: first index where cum[idx] > t.
    // Window 512 -> needs 10 steps. Once lo==hi the step is a provable no-op
    // (invariant: cum[hi] > t), and mid <= 511 so no OOB.
    int lo = 0, hi = LR_T;
    #pragma unroll
    for (int s = 0; s < 10; ++s) {
        int mid = (lo + hi) >> 1;
        if (__ldg(cum + mid) <= t) lo = mid + 1; else hi = mid;
    }
    int idx = min(lo, LR_T - 1);

    const float4* xrow = (const float4*)(x + ((size_t)b * LR_T + idx) * LR_D);
    float4 v = xrow[tid];
    asm volatile("st.global.cs.v4.f32 [%0], {%1,%2,%3,%4};"
                 :: "l"(orow + tid), "f"(v.x), "f"(v.y), "f"(v.z), "f"(v.w)
                 : "memory");
}

// ---------------------------------------------------------------------------
extern "C" void kernel_launch(void* const* d_in, const int* in_sizes, int n_in,
                              void* d_out, int out_size) {
    const float* x   = (const float*)d_in[0];   // [B, T, D] f32
    const float* dur = (const float*)d_in[1];   // [B, T]    f32
    float* out = (float*)d_out;                 // [B, t_out, D] f32

    const int t_out = out_size / (LR_B * LR_D);

    lr_scan_kernel<<<LR_B, LR_T>>>(dur);

    dim3 grid(t_out, LR_B);
    lr_gather_kernel<<<grid, 192>>>(x, out, t_out);
}

// round 3
// speedup vs baseline: 2.1440x; 2.1440x over previous
#include <cuda_runtime.h>
#include <cuda_bf16.h>

// Problem constants (from reference): B=32, T=512, D=768
#define LR_B 32
#define LR_T 512
#define LR_D 768
#define ZROWS 8   // output rows handled per zero-fill block

// Scratch (no cudaMalloc allowed): per-batch inclusive cumsum + totals
__device__ int g_cum[LR_B * LR_T];
__device__ int g_tot[LR_B];

// ---------------------------------------------------------------------------
// Kernel 1: per-batch rounded-duration inclusive scan.
// One block per batch, 512 threads, Hillis-Steele in shared memory.
// ---------------------------------------------------------------------------
__global__ void lr_scan_kernel(const float* __restrict__ dur) {
    const int b = blockIdx.x;
    const int i = threadIdx.x;
    __shared__ int s[LR_T];

    float d = dur[b * LR_T + i];
    // reps = floor(max(dur,0) + 0.5)  (identical fp32 ops to the reference)
    int r = (int)floorf(fmaxf(d, 0.0f) + 0.5f);
    s[i] = r;
    __syncthreads();

    #pragma unroll
    for (int off = 1; off < LR_T; off <<= 1) {
        int v = (i >= off) ? s[i - off] : 0;
        __syncthreads();
        s[i] += v;
        __syncthreads();
    }

    g_cum[b * LR_T + i] = s[i];
    if (i == LR_T - 1) g_tot[b] = s[i];
}

// ---------------------------------------------------------------------------
// Kernel 2: scatter/expand + tail zero-fill, fused into one launch.
//
// Blocks with blockIdx.x <  LR_T : scatter. Block (s, b) reads source row
//   x[b, s] ONCE (streaming loads — x has no reuse in this formulation),
//   then writes it reps = cum[s]-cum[s-1] times to consecutive output rows
//   starting at cum[s-1]. Stores are independent -> MLP = reps per thread.
//   No binary search anywhere.
//
// Blocks with blockIdx.x >= LR_T : zero-fill. Each handles ZROWS output rows,
//   zeroing those with t >= tot[b] (output is 0xAA-poisoned, the masked tail
//   must be explicitly zeroed). ~95% of these blocks exit doing nothing.
// ---------------------------------------------------------------------------
__global__ void __launch_bounds__(192) lr_expand_kernel(
    const float* __restrict__ x,
    float* __restrict__ out,
    int t_out)
{
    const int b   = blockIdx.y;
    const int tid = threadIdx.x;

    if (blockIdx.x < LR_T) {
        // ---- scatter path ----
        const int s = blockIdx.x;
        const int cs   = g_cum[b * LR_T + s];
        const int prev = (s == 0) ? 0 : g_cum[b * LR_T + s - 1];
        const int reps = cs - prev;
        if (reps == 0) return;

        // Stream-read this thread's float4 of the source row (no reuse).
        const float4* xq = (const float4*)(x + ((size_t)b * LR_T + s) * LR_D) + tid;
        float4 v;
        asm volatile("ld.global.cs.v4.f32 {%0,%1,%2,%3}, [%4];"
                     : "=f"(v.x), "=f"(v.y), "=f"(v.z), "=f"(v.w)
                     : "l"(xq));

        float4* obase = (float4*)(out + ((size_t)b * t_out + prev) * LR_D) + tid;
        const int stride4 = LR_D / 4;  // float4s per row

        #pragma unroll 4
        for (int r = 0; r < reps; ++r) {
            asm volatile("st.global.cs.v4.f32 [%0], {%1,%2,%3,%4};"
                         :: "l"(obase + (size_t)r * stride4),
                            "f"(v.x), "f"(v.y), "f"(v.z), "f"(v.w)
                         : "memory");
        }
    } else {
        // ---- zero-fill path ----
        const int tot = g_tot[b];
        const int t0  = (blockIdx.x - LR_T) * ZROWS;
        if (t0 + ZROWS <= tot) return;  // fully inside valid region

        const float4 z = make_float4(0.f, 0.f, 0.f, 0.f);
        #pragma unroll
        for (int r = 0; r < ZROWS; ++r) {
            const int t = t0 + r;
            if (t >= tot && t < t_out) {
                float4* orow = (float4*)(out + ((size_t)b * t_out + t) * LR_D) + tid;
                asm volatile("st.global.cs.v4.f32 [%0], {%1,%2,%3,%4};"
                             :: "l"(orow), "f"(z.x), "f"(z.y), "f"(z.z), "f"(z.w)
                             : "memory");
            }
        }
    }
}

// ---------------------------------------------------------------------------
extern "C" void kernel_launch(void* const* d_in, const int* in_sizes, int n_in,
                              void* d_out, int out_size) {
    const float* x   = (const float*)d_in[0];   // [B, T, D] f32
    const float* dur = (const float*)d_in[1];   // [B, T]    f32
    float* out = (float*)d_out;                 // [B, t_out, D] f32

    const int t_out = out_size / (LR_B * LR_D);

    lr_scan_kernel<<<LR_B, LR_T>>>(dur);

    const int zero_blocks = (t_out + ZROWS - 1) / ZROWS;
    dim3 grid(LR_T + zero_blocks, LR_B);
    lr_expand_kernel<<<grid, 192>>>(x, out, t_out);
}